// round 1
// baseline (speedup 1.0000x reference)
#include <cuda_runtime.h>

// GruAeModel: B=1024, S=1024, F=36 (12 raw + 4+4+8+8 emb), H=20.
// One warp per batch element, persistent single kernel (enc + dec), no grid sync.
// Weights register-resident, math via fma.rn.f32x2 (k-pair packed partial sums).

#define HH 20
#define FF 36
#define RR 12
#define BB 1024
#define SS 1024
#define WARPS_PER_BLOCK 8
#define NTHREADS (WARPS_PER_BLOCK * 32)

__device__ __forceinline__ unsigned long long ffma2(unsigned long long a,
                                                    unsigned long long b,
                                                    unsigned long long c) {
    unsigned long long d;
    asm("fma.rn.f32x2 %0, %1, %2, %3;" : "=l"(d) : "l"(a), "l"(b), "l"(c));
    return d;
}
__device__ __forceinline__ float fold2(unsigned long long a) {
    float lo = __uint_as_float((unsigned)a);
    float hi = __uint_as_float((unsigned)(a >> 32));
    return lo + hi;
}
// sigmoid / tanh via EX2+RCP (accurate to ~1e-6, far under 1e-3 tolerance)
__device__ __forceinline__ float sigf(float x) {
    float e = __expf(-x);
    return __fdividef(1.0f, 1.0f + e);
}
__device__ __forceinline__ float tanhfast(float x) {
    float e = __expf(2.0f * x);
    return 1.0f - __fdividef(2.0f, 1.0f + e);
}

__global__ __launch_bounds__(NTHREADS, 1) void gruae_kernel(
    const float* __restrict__ x, const int* __restrict__ oneh,
    const float* __restrict__ e0, const float* __restrict__ e1,
    const float* __restrict__ e2, const float* __restrict__ e3,
    const float* __restrict__ Wih1, const float* __restrict__ Whh1,
    const float* __restrict__ bih1, const float* __restrict__ bhh1,
    const float* __restrict__ Wih2, const float* __restrict__ Whh2,
    const float* __restrict__ bih2, const float* __restrict__ bhh2,
    const float* __restrict__ Wfc, const float* __restrict__ bfc,
    float* __restrict__ out) {
    // shared: embedding tables + per-warp state
    __shared__ __align__(16) float etab[1320];          // e0(40) e1(80)@40 e2(400)@120 e3(800)@520
    __shared__ __align__(16) float XS[WARPS_PER_BLOCK][40];   // xin (F=36, padded)
    __shared__ __align__(16) float HS[WARPS_PER_BLOCK][24];   // h (H=20, padded)
    __shared__ __align__(16) float GIs[WARPS_PER_BLOCK][60];
    __shared__ __align__(16) float GHs[WARPS_PER_BLOCK][60];

    const int tid = threadIdx.x;
    const int wid = tid >> 5;
    const int lane = tid & 31;

    for (int i = tid; i < 40; i += NTHREADS) etab[i] = e0[i];
    for (int i = tid; i < 80; i += NTHREADS) etab[40 + i] = e1[i];
    for (int i = tid; i < 400; i += NTHREADS) etab[120 + i] = e2[i];
    for (int i = tid; i < 800; i += NTHREADS) etab[520 + i] = e3[i];
    __syncthreads();

    const int b = blockIdx.x * WARPS_PER_BLOCK + wid;
    float* xsh = XS[wid];
    float* hsh = HS[wid];
    float* GI = GIs[wid];
    float* GH = GHs[wid];

    // ---- encoder weight load: lane l owns gates gA=l, gB=l+30 (l<30) ----
    const int gA = lane, gB = lane + 30;
    unsigned long long wiA[18], wiB[18], whA[10], whB[10];
    float biA = 0.f, biB = 0.f, bhA = 0.f, bhB = 0.f;
    if (lane < 30) {
        const unsigned long long* ra = (const unsigned long long*)(Wih1 + gA * FF);
        const unsigned long long* rb = (const unsigned long long*)(Wih1 + gB * FF);
#pragma unroll
        for (int j = 0; j < 18; j++) { wiA[j] = ra[j]; wiB[j] = rb[j]; }
        const unsigned long long* ha = (const unsigned long long*)(Whh1 + gA * HH);
        const unsigned long long* hb = (const unsigned long long*)(Whh1 + gB * HH);
#pragma unroll
        for (int j = 0; j < 10; j++) { whA[j] = ha[j]; whB[j] = hb[j]; }
        biA = bih1[gA]; biB = bih1[gB]; bhA = bhh1[gA]; bhB = bhh1[gB];
    }
    if (lane < HH) hsh[lane] = 0.0f;

    // ---- input prefetch (distance 3) ----
    const float* xb = x + (size_t)b * SS * RR;
    const int* ob = oneh + (size_t)b * SS * 4;
    float xp0 = 0.f, xp1 = 0.f, xp2 = 0.f;
    int op0 = 0, op1 = 0, op2 = 0;
    if (lane < RR) { xp0 = xb[lane]; xp1 = xb[RR + lane]; xp2 = xb[2 * RR + lane]; }
    if (lane >= 12 && lane < 16) {
        int c = lane - 12;
        op0 = ob[c]; op1 = ob[4 + c]; op2 = ob[8 + c];
    }
    float* origin = out + (size_t)b * SS * FF;
    float* xsout = out + (size_t)BB * SS * FF + (size_t)b * SS * FF;
    __syncwarp();

    // ================= encoder =================
    for (int t = 0; t < SS; t++) {
        int o0 = __shfl_sync(0xffffffffu, op0, 12);
        int o1 = __shfl_sync(0xffffffffu, op0, 13);
        int o2 = __shfl_sync(0xffffffffu, op0, 14);
        int o3 = __shfl_sync(0xffffffffu, op0, 15);
        // build xin, write origin
#pragma unroll
        for (int rep = 0; rep < 2; rep++) {
            int f = lane + rep * 32;
            if (f < FF) {
                float v;
                if (f < 12)      v = xp0;
                else if (f < 16) v = etab[o0 * 4 + (f - 12)];
                else if (f < 20) v = etab[40 + o1 * 4 + (f - 16)];
                else if (f < 28) v = etab[120 + o2 * 8 + (f - 20)];
                else             v = etab[520 + o3 * 8 + (f - 28)];
                xsh[f] = v;
                origin[(size_t)t * FF + f] = v;
            }
        }
        // rotate prefetch, issue next load
        xp0 = xp1; xp1 = xp2; op0 = op1; op1 = op2;
        int tn = t + 3;
        if (tn < SS) {
            if (lane < RR) xp2 = xb[(size_t)tn * RR + lane];
            if (lane >= 12 && lane < 16) op2 = ob[(size_t)tn * 4 + (lane - 12)];
        }
        __syncwarp();
        if (lane < 30) {
            unsigned long long ai = 0, bi = 0, ah = 0, bh = 0;
#pragma unroll
            for (int j = 0; j < 18; j++) {
                unsigned long long xk = *(const unsigned long long*)(xsh + 2 * j);
                ai = ffma2(wiA[j], xk, ai);
                bi = ffma2(wiB[j], xk, bi);
            }
#pragma unroll
            for (int j = 0; j < 10; j++) {
                unsigned long long hk = *(const unsigned long long*)(hsh + 2 * j);
                ah = ffma2(whA[j], hk, ah);
                bh = ffma2(whB[j], hk, bh);
            }
            GI[gA] = fold2(ai) + biA; GI[gB] = fold2(bi) + biB;
            GH[gA] = fold2(ah) + bhA; GH[gB] = fold2(bh) + bhB;
        }
        __syncwarp();
        if (lane < HH) {
            float r = sigf(GI[lane] + GH[lane]);
            float z = sigf(GI[20 + lane] + GH[20 + lane]);
            float n = tanhfast(GI[40 + lane] + r * GH[40 + lane]);
            hsh[lane] = (1.0f - z) * n + z * hsh[lane];
        }
        __syncwarp();
    }

    // ---- h = tanh(h_last) ----
    if (lane < HH) hsh[lane] = tanhfast(hsh[lane]);

    // ---- decoder weight load (reuse gate arrays) + Wfc ----
    if (lane < 30) {
        const unsigned long long* ra = (const unsigned long long*)(Wih2 + gA * FF);
        const unsigned long long* rb = (const unsigned long long*)(Wih2 + gB * FF);
#pragma unroll
        for (int j = 0; j < 18; j++) { wiA[j] = ra[j]; wiB[j] = rb[j]; }
        const unsigned long long* ha = (const unsigned long long*)(Whh2 + gA * HH);
        const unsigned long long* hb = (const unsigned long long*)(Whh2 + gB * HH);
#pragma unroll
        for (int j = 0; j < 10; j++) { whA[j] = ha[j]; whB[j] = hb[j]; }
        biA = bih2[gA]; biB = bih2[gB]; bhA = bhh2[gA]; bhB = bhh2[gB];
    }
    unsigned long long wf0[10], wf1[10];
    float bf0 = 0.f, bf1 = 0.f;
    if (lane < 18) {
        const unsigned long long* f0 = (const unsigned long long*)(Wfc + lane * HH);
        const unsigned long long* f1 = (const unsigned long long*)(Wfc + (lane + 18) * HH);
#pragma unroll
        for (int j = 0; j < 10; j++) { wf0[j] = f0[j]; wf1[j] = f1[j]; }
        bf0 = bfc[lane]; bf1 = bfc[lane + 18];
    }
    __syncwarp();

    // ---- x0 = tanh(h @ Wfc^T + bfc), written at flipped index S-1 ----
    if (lane < 18) {
        unsigned long long a0 = 0, a1 = 0;
#pragma unroll
        for (int j = 0; j < 10; j++) {
            unsigned long long hk = *(const unsigned long long*)(hsh + 2 * j);
            a0 = ffma2(wf0[j], hk, a0);
            a1 = ffma2(wf1[j], hk, a1);
        }
        float v0 = tanhfast(fold2(a0) + bf0);
        float v1 = tanhfast(fold2(a1) + bf1);
        xsh[lane] = v0; xsh[lane + 18] = v1;
        xsout[(size_t)(SS - 1) * FF + lane] = v0;
        xsout[(size_t)(SS - 1) * FF + lane + 18] = v1;
    }
    __syncwarp();

    // ================= decoder =================
    for (int t = 1; t < SS; t++) {
        if (lane < 30) {
            unsigned long long ai = 0, bi = 0, ah = 0, bh = 0;
#pragma unroll
            for (int j = 0; j < 18; j++) {
                unsigned long long xk = *(const unsigned long long*)(xsh + 2 * j);
                ai = ffma2(wiA[j], xk, ai);
                bi = ffma2(wiB[j], xk, bi);
            }
#pragma unroll
            for (int j = 0; j < 10; j++) {
                unsigned long long hk = *(const unsigned long long*)(hsh + 2 * j);
                ah = ffma2(whA[j], hk, ah);
                bh = ffma2(whB[j], hk, bh);
            }
            GI[gA] = fold2(ai) + biA; GI[gB] = fold2(bi) + biB;
            GH[gA] = fold2(ah) + bhA; GH[gB] = fold2(bh) + bhB;
        }
        __syncwarp();
        if (lane < HH) {
            float r = sigf(GI[lane] + GH[lane]);
            float z = sigf(GI[20 + lane] + GH[20 + lane]);
            float n = tanhfast(GI[40 + lane] + r * GH[40 + lane]);
            hsh[lane] = tanhfast((1.0f - z) * n + z * hsh[lane]);
        }
        __syncwarp();
        if (lane < 18) {
            unsigned long long a0 = 0, a1 = 0;
#pragma unroll
            for (int j = 0; j < 10; j++) {
                unsigned long long hk = *(const unsigned long long*)(hsh + 2 * j);
                a0 = ffma2(wf0[j], hk, a0);
                a1 = ffma2(wf1[j], hk, a1);
            }
            float v0 = tanhfast(fold2(a0) + bf0);
            float v1 = tanhfast(fold2(a1) + bf1);
            xsh[lane] = v0; xsh[lane + 18] = v1;
            size_t row = (size_t)(SS - 1 - t) * FF;
            xsout[row + lane] = v0;
            xsout[row + lane + 18] = v1;
        }
        __syncwarp();
    }
}

extern "C" void kernel_launch(void* const* d_in, const int* in_sizes, int n_in,
                              void* d_out, int out_size) {
    const float* x    = (const float*)d_in[0];
    const int*   oneh = (const int*)d_in[1];
    const float* e0   = (const float*)d_in[2];
    const float* e1   = (const float*)d_in[3];
    const float* e2   = (const float*)d_in[4];
    const float* e3   = (const float*)d_in[5];
    const float* Wih1 = (const float*)d_in[6];
    const float* Whh1 = (const float*)d_in[7];
    const float* bih1 = (const float*)d_in[8];
    const float* bhh1 = (const float*)d_in[9];
    const float* Wih2 = (const float*)d_in[10];
    const float* Whh2 = (const float*)d_in[11];
    const float* bih2 = (const float*)d_in[12];
    const float* bhh2 = (const float*)d_in[13];
    const float* Wfc  = (const float*)d_in[14];
    const float* bfc  = (const float*)d_in[15];

    gruae_kernel<<<BB / WARPS_PER_BLOCK, NTHREADS>>>(
        x, oneh, e0, e1, e2, e3, Wih1, Whh1, bih1, bhh1,
        Wih2, Whh2, bih2, bhh2, Wfc, bfc, (float*)d_out);
}